// round 12
// baseline (speedup 1.0000x reference)
#include <cuda_runtime.h>
#include <cuda_bf16.h>

// Problem constants (fixed by the dataset)
#define NN 40000
#define EE 640000
#define GG 64
#define F1 128
#define F2 64

typedef unsigned long long ull;

// ---------------- scratch (no allocations allowed) ----------------
__device__ __nv_bfloat16 g_hbf[NN * F1];  // GEMM output (bf16) for gathers
__device__ float g_hb[NN * F1];           // agg+LN output (fp32, feeds next GEMM / pool)
__device__ float g_ss1[2 * NN], g_ds1[2 * NN];   // per-column-block partial scores (layer1)
__device__ float g_ss2[NN], g_ds2[NN];           // layer2 (single column block)
__device__ int   g_deg[NN];               // zero at start of every run (see scatter)
__device__ int   g_rowptr[NN + 1];
__device__ int   g_rowptr2[NN];           // destructive cursor copy
__device__ int   g_csrsrc[EE];

__device__ __forceinline__ float lrelu(float x) { return x > 0.f ? x : 0.2f * x; }

// ---------------- CSR build ----------------
// 4 edges per thread (EE % 4 == 0)
__global__ void count_kernel(const int* __restrict__ dst) {
    int i = blockIdx.x * blockDim.x + threadIdx.x;
    if (i < EE / 4) {
        int4 d = ((const int4*)dst)[i];
        atomicAdd(&g_deg[d.x], 1);
        atomicAdd(&g_deg[d.y], 1);
        atomicAdd(&g_deg[d.z], 1);
        atomicAdd(&g_deg[d.w], 1);
    }
}

__device__ __forceinline__ int block_excl_scan(int v) {
    __shared__ int ws[8];
    int tid = threadIdx.x;
    int lane = tid & 31, wid = tid >> 5;
    int x = v;
    #pragma unroll
    for (int off = 1; off < 32; off <<= 1) {
        int y = __shfl_up_sync(0xffffffffu, x, off);
        if (lane >= off) x += y;
    }
    if (lane == 31) ws[wid] = x;
    __syncthreads();
    if (wid == 0) {
        int w = (lane < 8) ? ws[lane] : 0;
        #pragma unroll
        for (int off = 1; off < 8; off <<= 1) {
            int y = __shfl_up_sync(0xffffffffu, w, off);
            if (lane >= off) w += y;
        }
        if (lane < 8) ws[lane] = w;
    }
    __syncthreads();
    int add = (wid > 0) ? ws[wid - 1] : 0;
    return x - v + add;   // exclusive
}

// one-launch scan: each block recomputes its global offset itself
__global__ void scan_kernel() {
    __shared__ int red[8];
    __shared__ int s_off;
    int b = blockIdx.x, t = threadIdx.x;
    int lane = t & 31, wid = t >> 5;
    int lim = b * 256;
    int part = 0;
    for (int j = t; j < lim; j += 256) part += g_deg[j];
    #pragma unroll
    for (int off = 16; off > 0; off >>= 1) part += __shfl_xor_sync(0xffffffffu, part, off);
    if (lane == 0) red[wid] = part;
    __syncthreads();
    if (t == 0) {
        int s = 0;
        #pragma unroll
        for (int k = 0; k < 8; ++k) s += red[k];
        s_off = s;
    }
    __syncthreads();
    int off0 = s_off;
    int i = b * 256 + t;
    int v = (i < NN) ? g_deg[i] : 0;
    int e = block_excl_scan(v);
    if (i < NN) {
        g_rowptr[i]  = off0 + e;
        g_rowptr2[i] = off0 + e;   // destructive cursor copy
    }
    if (i == NN - 1) g_rowptr[NN] = off0 + e + v;
}

// single-atomic scatter (destructive rowptr2 cursor); also re-zeroes deg.
__global__ void scatter_kernel(const int* __restrict__ src, const int* __restrict__ dst) {
    int i = blockIdx.x * blockDim.x + threadIdx.x;
    if (i < NN) g_deg[i] = 0;
    if (i < EE / 4) {
        int4 d = ((const int4*)dst)[i];
        int4 s = ((const int4*)src)[i];
        g_csrsrc[atomicAdd(&g_rowptr2[d.x], 1)] = s.x;
        g_csrsrc[atomicAdd(&g_rowptr2[d.y], 1)] = s.y;
        g_csrsrc[atomicAdd(&g_rowptr2[d.z], 1)] = s.z;
        g_csrsrc[atomicAdd(&g_rowptr2[d.w], 1)] = s.w;
    }
}

// ---------------- tf32 tensor-core GEMM, full-K resident, single sync ----------------
__device__ __forceinline__ unsigned f2tf32(float x) {
    unsigned r; asm("cvt.rna.tf32.f32 %0, %1;" : "=r"(r) : "f"(x)); return r;
}
__device__ __forceinline__ void mma_tf32(float* d, const unsigned* a, const unsigned* b) {
    asm volatile(
        "mma.sync.aligned.m16n8k8.row.col.f32.tf32.tf32.f32 "
        "{%0,%1,%2,%3}, {%4,%5,%6,%7}, {%8,%9}, {%0,%1,%2,%3};"
        : "+f"(d[0]), "+f"(d[1]), "+f"(d[2]), "+f"(d[3])
        : "r"(a[0]), "r"(a[1]), "r"(a[2]), "r"(a[3]), "r"(b[0]), "r"(b[1]));
}

// BM=128, BN=64, K=128 fully resident. 128 threads (4 warps); warp w owns m-tiles 2w, 2w+1.
// Fragment word layout (verified round-9, fid extended by k-block):
//  A: word = ((mtile*8 + kb)*2 + kstep)*128 + slot*32 + lane
//     lane = (r16%8)*4 + (k8%4), slot = (r16>=8) + 2*(k8>=4)
//  B: word = ((ntile*8 + kb)*2 + kstep)*64 + slot*32 + lane
//     lane = n8*4 + (k8%4), slot = (k8>=4)
#define A_WORDS (16384)
#define B_WORDS (8192)
__global__ __launch_bounds__(128)
void gemm_tf32(const float* __restrict__ A, const float* __restrict__ W,
               __nv_bfloat16* __restrict__ Cb,
               float* __restrict__ ss, float* __restrict__ ds,
               const float* __restrict__ asrc, const float* __restrict__ adst,
               int M, int Nout) {
    extern __shared__ unsigned smem[];
    unsigned* As = smem;            // 16384 words (64 KB)
    unsigned* Ws = smem + A_WORDS;  // 8192 words (32 KB)
    const int K = 128;

    int tid = threadIdx.x;
    int w = tid >> 5, lane = tid & 31;
    int gid = lane >> 2, tig = lane & 3;
    int mBase = blockIdx.x * 128;
    int nBase = blockIdx.y * 64;
    int yoff = blockIdx.y * M;

    int lrow = tid >> 2;                    // 0..31
    int lkc  = (tid & 3) * 4;               // 0,4,8,12
    int kstepL = lkc >> 3;                  // 0/1
    int khL    = (lkc >> 2) & 1;            // k-half within k8

    // ---- fill entire K in one shot ----
    #pragma unroll
    for (int kb = 0; kb < 8; ++kb) {
        #pragma unroll
        for (int i = 0; i < 4; ++i) {
            int r = lrow + i * 32;          // 0..127
            int gr = mBase + r;
            float4 v = (gr < M) ? *(const float4*)&A[(size_t)gr * K + kb * 16 + lkc]
                                : make_float4(0.f, 0.f, 0.f, 0.f);
            int mtile = r >> 4, r16 = r & 15;
            int slot = (r16 >> 3) + 2 * khL;
            int addr = ((mtile * 8 + kb) * 2 + kstepL) * 128 + slot * 32 + (r16 & 7) * 4;
            uint4 u;
            u.x = f2tf32(v.x); u.y = f2tf32(v.y); u.z = f2tf32(v.z); u.w = f2tf32(v.w);
            *(uint4*)&As[addr] = u;
        }
        #pragma unroll
        for (int i = 0; i < 2; ++i) {
            int wr = lrow + i * 32;         // 0..63
            float4 v = *(const float4*)&W[(size_t)(nBase + wr) * K + kb * 16 + lkc];
            int ntile = wr >> 3, n8 = wr & 7;
            int addr = ((ntile * 8 + kb) * 2 + kstepL) * 64 + khL * 32 + n8 * 4;
            uint4 u;
            u.x = f2tf32(v.x); u.y = f2tf32(v.y); u.z = f2tf32(v.z); u.w = f2tf32(v.w);
            *(uint4*)&Ws[addr] = u;
        }
    }
    __syncthreads();

    float dacc[2][8][4];
    #pragma unroll
    for (int mt = 0; mt < 2; ++mt)
        #pragma unroll
        for (int nt = 0; nt < 8; ++nt)
            #pragma unroll
            for (int q = 0; q < 4; ++q) dacc[mt][nt][q] = 0.f;

    for (int kb = 0; kb < 8; ++kb) {
        #pragma unroll
        for (int kstep = 0; kstep < 2; ++kstep) {
            unsigned a[2][4], b[8][2];
            #pragma unroll
            for (int mt = 0; mt < 2; ++mt) {
                int base = (((2 * w + mt) * 8 + kb) * 2 + kstep) * 128 + lane;
                a[mt][0] = As[base];
                a[mt][1] = As[base + 32];
                a[mt][2] = As[base + 64];
                a[mt][3] = As[base + 96];
            }
            #pragma unroll
            for (int nt = 0; nt < 8; ++nt) {
                int base = ((nt * 8 + kb) * 2 + kstep) * 64 + lane;
                b[nt][0] = Ws[base];
                b[nt][1] = Ws[base + 32];
            }
            #pragma unroll
            for (int mt = 0; mt < 2; ++mt)
                #pragma unroll
                for (int nt = 0; nt < 8; ++nt)
                    mma_tf32(dacc[mt][nt], a[mt], b[nt]);
        }
    }

    // attention vectors for this thread's columns (2 per ntile)
    float2 vs_[8], vd_[8];
    #pragma unroll
    for (int nt = 0; nt < 8; ++nt) {
        vs_[nt] = *(const float2*)&asrc[nBase + nt * 8 + 2 * tig];
        vd_[nt] = *(const float2*)&adst[nBase + nt * 8 + 2 * tig];
    }

    #pragma unroll
    for (int mt = 0; mt < 2; ++mt) {
        int r0 = mBase + w * 32 + mt * 16 + gid;   // row of d[0],d[1]
        int r1 = r0 + 8;                           // row of d[2],d[3]

        float sl = 0.f, dl = 0.f, sh = 0.f, dh = 0.f;
        #pragma unroll
        for (int nt = 0; nt < 8; ++nt) {
            sl += dacc[mt][nt][0] * vs_[nt].x + dacc[mt][nt][1] * vs_[nt].y;
            dl += dacc[mt][nt][0] * vd_[nt].x + dacc[mt][nt][1] * vd_[nt].y;
            sh += dacc[mt][nt][2] * vs_[nt].x + dacc[mt][nt][3] * vs_[nt].y;
            dh += dacc[mt][nt][2] * vd_[nt].x + dacc[mt][nt][3] * vd_[nt].y;
        }
        #pragma unroll
        for (int off = 1; off < 4; off <<= 1) {
            sl += __shfl_xor_sync(0xffffffffu, sl, off);
            dl += __shfl_xor_sync(0xffffffffu, dl, off);
            sh += __shfl_xor_sync(0xffffffffu, sh, off);
            dh += __shfl_xor_sync(0xffffffffu, dh, off);
        }
        if (tig == 0) {
            if (r0 < M) { ss[yoff + r0] = sl; ds[yoff + r0] = dl; }
            if (r1 < M) { ss[yoff + r1] = sh; ds[yoff + r1] = dh; }
        }

        #pragma unroll
        for (int nt = 0; nt < 8; ++nt) {
            int col = nBase + nt * 8 + 2 * tig;
            if (r0 < M) {
                __nv_bfloat162 p = __floats2bfloat162_rn(dacc[mt][nt][0], dacc[mt][nt][1]);
                *(unsigned*)&Cb[(size_t)r0 * Nout + col] = *(unsigned*)&p;
            }
            if (r1 < M) {
                __nv_bfloat162 p = __floats2bfloat162_rn(dacc[mt][nt][2], dacc[mt][nt][3]);
                *(unsigned*)&Cb[(size_t)r1 * Nout + col] = *(unsigned*)&p;
            }
        }
    }
}

// ---------------- bf16 row loads ----------------
__device__ __forceinline__ float4 ldrow128(const __nv_bfloat16* base, int row, int lane) {
    uint2 u = ((const uint2*)(base + (size_t)row * 128))[lane];
    __nv_bfloat162 p0 = *(__nv_bfloat162*)&u.x;
    __nv_bfloat162 p1 = *(__nv_bfloat162*)&u.y;
    float2 f0 = __bfloat1622float2(p0);
    float2 f1 = __bfloat1622float2(p1);
    return make_float4(f0.x, f0.y, f1.x, f1.y);
}
__device__ __forceinline__ float2 ldrow64(const __nv_bfloat16* base, int row, int lane) {
    unsigned u = ((const unsigned*)(base + (size_t)row * 64))[lane];
    __nv_bfloat162 p = *(__nv_bfloat162*)&u;
    return __bfloat1622float2(p);
}

// ---------------- fused GAT aggregate + bias + ReLU + LayerNorm ----------------
template <int F, bool TWO>
__global__ void agg_kernel(const __nv_bfloat16* __restrict__ hbf,
                           const float* __restrict__ ssp, const float* __restrict__ dsp,
                           const float* __restrict__ bias,
                           const float* __restrict__ gamma,
                           const float* __restrict__ beta,
                           float* __restrict__ out) {
    constexpr int VL = F / 32;
    int warp = (blockIdx.x * blockDim.x + threadIdx.x) >> 5;
    int lane = threadIdx.x & 31;
    if (warp >= NN) return;
    int n = warp;
    float dsn = TWO ? (dsp[n] + dsp[n + NN]) : dsp[n];
    int s0 = g_rowptr[n], s1 = g_rowptr[n + 1];

    auto score = [&](int s) -> float {
        return TWO ? (ssp[s] + ssp[s + NN]) : ssp[s];
    };

    float acc[VL];
    float w = __expf(lrelu(score(n) + dsn));   // self loop
    float z = w;
    if constexpr (VL == 4) {
        float4 t = ldrow128(hbf, n, lane);
        acc[0] = w * t.x; acc[1] = w * t.y; acc[2] = w * t.z; acc[3] = w * t.w;
    } else {
        float2 t = ldrow64(hbf, n, lane);
        acc[0] = w * t.x; acc[1] = w * t.y;
    }

    int i = s0;
    for (; i + 8 <= s1; i += 8) {
        int s[8];
        #pragma unroll
        for (int k = 0; k < 8; ++k) s[k] = g_csrsrc[i + k];
        float sc[8];
        #pragma unroll
        for (int k = 0; k < 8; ++k) sc[k] = score(s[k]);
        if constexpr (VL == 4) {
            float4 t[8];
            #pragma unroll
            for (int k = 0; k < 8; ++k) t[k] = ldrow128(hbf, s[k], lane);
            float wv[8];
            #pragma unroll
            for (int k = 0; k < 8; ++k) { wv[k] = __expf(lrelu(sc[k] + dsn)); z += wv[k]; }
            #pragma unroll
            for (int k = 0; k < 8; ++k) {
                acc[0] += wv[k] * t[k].x;
                acc[1] += wv[k] * t[k].y;
                acc[2] += wv[k] * t[k].z;
                acc[3] += wv[k] * t[k].w;
            }
        } else {
            float2 t[8];
            #pragma unroll
            for (int k = 0; k < 8; ++k) t[k] = ldrow64(hbf, s[k], lane);
            float wv[8];
            #pragma unroll
            for (int k = 0; k < 8; ++k) { wv[k] = __expf(lrelu(sc[k] + dsn)); z += wv[k]; }
            #pragma unroll
            for (int k = 0; k < 8; ++k) {
                acc[0] += wv[k] * t[k].x;
                acc[1] += wv[k] * t[k].y;
            }
        }
    }
    for (; i < s1; ++i) {
        int s = g_csrsrc[i];
        float ww = __expf(lrelu(score(s) + dsn));
        z += ww;
        if constexpr (VL == 4) {
            float4 t = ldrow128(hbf, s, lane);
            acc[0] += ww * t.x; acc[1] += ww * t.y; acc[2] += ww * t.z; acc[3] += ww * t.w;
        } else {
            float2 t = ldrow64(hbf, s, lane);
            acc[0] += ww * t.x; acc[1] += ww * t.y;
        }
    }

    float inv = 1.f / z;
    float v[VL];
    float sum = 0.f;
    #pragma unroll
    for (int j = 0; j < VL; ++j) {
        v[j] = fmaxf(acc[j] * inv + bias[lane * VL + j], 0.f);  // bias + ReLU
        sum += v[j];
    }
    #pragma unroll
    for (int off = 16; off > 0; off >>= 1)
        sum += __shfl_xor_sync(0xffffffffu, sum, off);
    float mean = sum * (1.f / F);
    float vs = 0.f;
    #pragma unroll
    for (int j = 0; j < VL; ++j) {
        float d = v[j] - mean;
        vs += d * d;
    }
    #pragma unroll
    for (int off = 16; off > 0; off >>= 1)
        vs += __shfl_xor_sync(0xffffffffu, vs, off);
    float var = vs * (1.f / F);
    float r = rsqrtf(var + 1e-5f);
    if constexpr (VL == 4) {
        float4 gv = ((const float4*)gamma)[lane];
        float4 bv = ((const float4*)beta)[lane];
        float4 o;
        o.x = gv.x * (v[0] - mean) * r + bv.x;
        o.y = gv.y * (v[1] - mean) * r + bv.y;
        o.z = gv.z * (v[2] - mean) * r + bv.z;
        o.w = gv.w * (v[3] - mean) * r + bv.w;
        ((float4*)&out[(size_t)n * F])[lane] = o;
    } else {
        float2 gv = ((const float2*)gamma)[lane];
        float2 bv = ((const float2*)beta)[lane];
        float2 o;
        o.x = gv.x * (v[0] - mean) * r + bv.x;
        o.y = gv.y * (v[1] - mean) * r + bv.y;
        ((float2*)&out[(size_t)n * F])[lane] = o;
    }
}

// ---------------- fused pool + head: one block per graph (batch is sorted) ----------------
__global__ void poolhead_kernel(const float* __restrict__ h, const int* __restrict__ batch,
                                const float* __restrict__ Wl, const float* __restrict__ bl,
                                const float* __restrict__ Wc, const float* __restrict__ bc,
                                float* __restrict__ out) {
    __shared__ float psum[4][F2];
    __shared__ float p[F2];
    __shared__ int range[2];
    __shared__ float red[2];
    int g = blockIdx.x;
    int t = threadIdx.x;
    int f = t & 63, q = t >> 6;

    if (t < 2) {
        int val = g + t;
        int lo = 0, hi = NN;
        while (lo < hi) {
            int mid = (lo + hi) >> 1;
            if (batch[mid] < val) lo = mid + 1; else hi = mid;
        }
        range[t] = lo;
    }
    __syncthreads();
    int lo = range[0], hi = range[1];

    float acc = 0.f;
    for (int n = lo + q; n < hi; n += 4) acc += h[(size_t)n * F2 + f];
    psum[q][f] = acc;
    __syncthreads();

    if (t < F2) {
        float cnt = (float)(hi - lo);
        float s = psum[0][t] + psum[1][t] + psum[2][t] + psum[3][t];
        p[t] = s / fmaxf(cnt, 1.f);
    }
    __syncthreads();

    if (t < F2) {
        float lin = bl[t];
        #pragma unroll 8
        for (int j = 0; j < F2; ++j) lin += p[j] * Wl[t * F2 + j];
        float part = lin * Wc[t];
        #pragma unroll
        for (int off = 16; off > 0; off >>= 1)
            part += __shfl_xor_sync(0xffffffffu, part, off);
        if ((t & 31) == 0) red[t >> 5] = part;
    }
    __syncthreads();
    if (t == 0) out[g] = red[0] + red[1] + bc[0];
}

// ---------------- launch ----------------
extern "C" void kernel_launch(void* const* d_in, const int* in_sizes, int n_in,
                              void* d_out, int out_size) {
    const float* x    = (const float*)d_in[0];
    const int*   ei   = (const int*)d_in[1];
    const int*   batch= (const int*)d_in[2];
    const float* W1   = (const float*)d_in[3];
    const float* a1s  = (const float*)d_in[4];
    const float* a1d  = (const float*)d_in[5];
    const float* b1   = (const float*)d_in[6];
    const float* g1   = (const float*)d_in[7];
    const float* be1  = (const float*)d_in[8];
    const float* W2   = (const float*)d_in[9];
    const float* a2s  = (const float*)d_in[10];
    const float* a2d  = (const float*)d_in[11];
    const float* b2   = (const float*)d_in[12];
    const float* g2   = (const float*)d_in[13];
    const float* be2  = (const float*)d_in[14];
    const float* Wl   = (const float*)d_in[15];
    const float* bl   = (const float*)d_in[16];
    const float* Wc   = (const float*)d_in[17];
    const float* bc   = (const float*)d_in[18];
    float* out = (float*)d_out;

    const int* src = ei;
    const int* dst = ei + EE;

    __nv_bfloat16* phbf;
    float *phb, *pss1, *pds1, *pss2, *pds2;
    cudaGetSymbolAddress((void**)&phbf, g_hbf);
    cudaGetSymbolAddress((void**)&phb,  g_hb);
    cudaGetSymbolAddress((void**)&pss1, g_ss1);
    cudaGetSymbolAddress((void**)&pds1, g_ds1);
    cudaGetSymbolAddress((void**)&pss2, g_ss2);
    cudaGetSymbolAddress((void**)&pds2, g_ds2);

    const int GEMM_SMEM = (A_WORDS + B_WORDS) * 4;   // 96 KB

    // side stream + fork/join events (created once; host-side objects only)
    static cudaStream_t s1 = nullptr;
    static cudaEvent_t eFork = nullptr, eJoin = nullptr;
    if (s1 == nullptr) {
        cudaStreamCreateWithFlags(&s1, cudaStreamNonBlocking);
        cudaEventCreateWithFlags(&eFork, cudaEventDisableTiming);
        cudaEventCreateWithFlags(&eJoin, cudaEventDisableTiming);
        cudaFuncSetAttribute(gemm_tf32, cudaFuncAttributeMaxDynamicSharedMemorySize, GEMM_SMEM);
    }

    const int NB = (NN + 255) / 256;   // 157

    // fork: CSR build chain on s1, GEMM1 on main stream
    cudaEventRecord(eFork, 0);
    cudaStreamWaitEvent(s1, eFork, 0);

    count_kernel<<<(EE / 4 + 255) / 256, 256, 0, s1>>>(dst);
    scan_kernel<<<NB, 256, 0, s1>>>();
    scatter_kernel<<<(EE / 4 + 255) / 256, 256, 0, s1>>>(src, dst);
    cudaEventRecord(eJoin, s1);

    // layer 1 GEMM (independent of CSR)
    gemm_tf32<<<dim3((NN + 127) / 128, F1 / 64), 128, GEMM_SMEM>>>(
        x, W1, phbf, pss1, pds1, a1s, a1d, NN, F1);

    // join: agg1 needs CSR + GEMM1
    cudaStreamWaitEvent(0, eJoin, 0);
    agg_kernel<F1, true><<<(NN * 32 + 255) / 256, 256>>>(phbf, pss1, pds1, b1, g1, be1, phb);

    // layer 2
    gemm_tf32<<<dim3((NN + 127) / 128, F2 / 64), 128, GEMM_SMEM>>>(
        phb, W2, phbf, pss2, pds2, a2s, a2d, NN, F2);
    agg_kernel<F2, false><<<(NN * 32 + 255) / 256, 256>>>(phbf, pss2, pds2, b2, g2, be2, phb);

    // fused pool + head
    poolhead_kernel<<<GG, 256>>>(phb, batch, Wl, bl, Wc, bc, out);
}

// round 14
// speedup vs baseline: 1.0386x; 1.0386x over previous
#include <cuda_runtime.h>
#include <cuda_bf16.h>

// Problem constants (fixed by the dataset)
#define NN 40000
#define EE 640000
#define GG 64
#define F1 128
#define F2 64

typedef unsigned long long ull;

// ---------------- scratch (no allocations allowed) ----------------
__device__ __nv_bfloat16 g_hbf[NN * F1];  // GEMM output (bf16) for gathers
__device__ float g_hb[NN * F1];           // agg+LN output (fp32, feeds next GEMM / pool)
__device__ float g_ss1[2 * NN], g_ds1[2 * NN];   // per-column-block partial scores (layer1)
__device__ float g_ss2[NN], g_ds2[NN];           // layer2 (single column block)
__device__ int   g_deg[NN];               // zero at start of every run (see scatter)
__device__ int   g_rowptr[NN + 1];
__device__ int   g_rowptr2[NN];           // destructive cursor copy
__device__ int   g_csrsrc[EE];

__device__ __forceinline__ float lrelu(float x) { return x > 0.f ? x : 0.2f * x; }

// ---------------- CSR build ----------------
// 4 edges per thread (EE % 4 == 0)
__global__ void count_kernel(const int* __restrict__ dst) {
    int i = blockIdx.x * blockDim.x + threadIdx.x;
    if (i < EE / 4) {
        int4 d = ((const int4*)dst)[i];
        atomicAdd(&g_deg[d.x], 1);
        atomicAdd(&g_deg[d.y], 1);
        atomicAdd(&g_deg[d.z], 1);
        atomicAdd(&g_deg[d.w], 1);
    }
}

__device__ __forceinline__ int block_excl_scan(int v) {
    __shared__ int ws[8];
    int tid = threadIdx.x;
    int lane = tid & 31, wid = tid >> 5;
    int x = v;
    #pragma unroll
    for (int off = 1; off < 32; off <<= 1) {
        int y = __shfl_up_sync(0xffffffffu, x, off);
        if (lane >= off) x += y;
    }
    if (lane == 31) ws[wid] = x;
    __syncthreads();
    if (wid == 0) {
        int w = (lane < 8) ? ws[lane] : 0;
        #pragma unroll
        for (int off = 1; off < 8; off <<= 1) {
            int y = __shfl_up_sync(0xffffffffu, w, off);
            if (lane >= off) w += y;
        }
        if (lane < 8) ws[lane] = w;
    }
    __syncthreads();
    int add = (wid > 0) ? ws[wid - 1] : 0;
    return x - v + add;   // exclusive
}

// one-launch scan: each block recomputes its global offset itself
__global__ void scan_kernel() {
    __shared__ int red[8];
    __shared__ int s_off;
    int b = blockIdx.x, t = threadIdx.x;
    int lane = t & 31, wid = t >> 5;
    int lim = b * 256;
    int part = 0;
    for (int j = t; j < lim; j += 256) part += g_deg[j];
    #pragma unroll
    for (int off = 16; off > 0; off >>= 1) part += __shfl_xor_sync(0xffffffffu, part, off);
    if (lane == 0) red[wid] = part;
    __syncthreads();
    if (t == 0) {
        int s = 0;
        #pragma unroll
        for (int k = 0; k < 8; ++k) s += red[k];
        s_off = s;
    }
    __syncthreads();
    int off0 = s_off;
    int i = b * 256 + t;
    int v = (i < NN) ? g_deg[i] : 0;
    int e = block_excl_scan(v);
    if (i < NN) {
        g_rowptr[i]  = off0 + e;
        g_rowptr2[i] = off0 + e;   // destructive cursor copy
    }
    if (i == NN - 1) g_rowptr[NN] = off0 + e + v;
}

// single-atomic scatter (destructive rowptr2 cursor); also re-zeroes deg.
__global__ void scatter_kernel(const int* __restrict__ src, const int* __restrict__ dst) {
    int i = blockIdx.x * blockDim.x + threadIdx.x;
    if (i < NN) g_deg[i] = 0;
    if (i < EE / 4) {
        int4 d = ((const int4*)dst)[i];
        int4 s = ((const int4*)src)[i];
        g_csrsrc[atomicAdd(&g_rowptr2[d.x], 1)] = s.x;
        g_csrsrc[atomicAdd(&g_rowptr2[d.y], 1)] = s.y;
        g_csrsrc[atomicAdd(&g_rowptr2[d.z], 1)] = s.z;
        g_csrsrc[atomicAdd(&g_rowptr2[d.w], 1)] = s.w;
    }
}

// ---------------- tf32 tensor-core GEMM with fused score epilogue ----------------
// (verified round-9/11 version: 128 threads, conflict-free [slot][lane] layout)
__device__ __forceinline__ unsigned f2tf32(float x) {
    unsigned r; asm("cvt.rna.tf32.f32 %0, %1;" : "=r"(r) : "f"(x)); return r;
}
__device__ __forceinline__ void mma_tf32(float* d, const unsigned* a, const unsigned* b) {
    asm volatile(
        "mma.sync.aligned.m16n8k8.row.col.f32.tf32.tf32.f32 "
        "{%0,%1,%2,%3}, {%4,%5,%6,%7}, {%8,%9}, {%0,%1,%2,%3};"
        : "+f"(d[0]), "+f"(d[1]), "+f"(d[2]), "+f"(d[3])
        : "r"(a[0]), "r"(a[1]), "r"(a[2]), "r"(a[3]), "r"(b[0]), "r"(b[1]));
}

__global__ __launch_bounds__(128)
void gemm_tf32(const float* __restrict__ A, const float* __restrict__ W,
               __nv_bfloat16* __restrict__ Cb,
               float* __restrict__ ss, float* __restrict__ ds,
               const float* __restrict__ asrc, const float* __restrict__ adst,
               int M, int Nout, int K) {
    __shared__ unsigned As[2][16 * 128];
    __shared__ unsigned Ws[2][16 * 64];

    int tid = threadIdx.x;
    int w = tid >> 5, lane = tid & 31;
    int gid = lane >> 2, tig = lane & 3;
    int mBase = blockIdx.x * 128;
    int nBase = blockIdx.y * 64;
    int yoff = blockIdx.y * M;

    int lrow = tid >> 2;                    // 0..31
    int lkc  = (tid & 3) * 4;               // 0,4,8,12
    int kstepL = lkc >> 3;                  // 0/1
    int khL    = (lkc >> 2) & 1;            // k-half within k8

    float dacc[2][8][4];
    #pragma unroll
    for (int mt = 0; mt < 2; ++mt)
        #pragma unroll
        for (int nt = 0; nt < 8; ++nt)
            #pragma unroll
            for (int q = 0; q < 4; ++q) dacc[mt][nt][q] = 0.f;

    auto fill = [&](int kt, int buf) {
        #pragma unroll
        for (int i = 0; i < 4; ++i) {
            int r = lrow + i * 32;          // 0..127
            int gr = mBase + r;
            float4 v = (gr < M) ? *(const float4*)&A[(size_t)gr * K + kt + lkc]
                                : make_float4(0.f, 0.f, 0.f, 0.f);
            int mtile = r >> 4, r16 = r & 15;
            int slot = (r16 >> 3) + 2 * khL;
            int addr = (mtile * 2 + kstepL) * 128 + slot * 32 + (r16 & 7) * 4;
            uint4 u;
            u.x = f2tf32(v.x); u.y = f2tf32(v.y); u.z = f2tf32(v.z); u.w = f2tf32(v.w);
            *(uint4*)&As[buf][addr] = u;
        }
        #pragma unroll
        for (int i = 0; i < 2; ++i) {
            int wr = lrow + i * 32;         // 0..63
            float4 v = *(const float4*)&W[(size_t)(nBase + wr) * K + kt + lkc];
            int ntile = wr >> 3, n8 = wr & 7;
            int addr = (ntile * 2 + kstepL) * 64 + khL * 32 + n8 * 4;
            uint4 u;
            u.x = f2tf32(v.x); u.y = f2tf32(v.y); u.z = f2tf32(v.z); u.w = f2tf32(v.w);
            *(uint4*)&Ws[buf][addr] = u;
        }
    };

    fill(0, 0);
    __syncthreads();

    int cur = 0;
    for (int kt = 0; kt < K; kt += 16) {
        if (kt + 16 < K) fill(kt + 16, cur ^ 1);
        #pragma unroll
        for (int kstep = 0; kstep < 2; ++kstep) {
            unsigned a[2][4], b[8][2];
            #pragma unroll
            for (int mt = 0; mt < 2; ++mt) {
                int base = ((2 * w + mt) * 2 + kstep) * 128 + lane;
                a[mt][0] = As[cur][base];
                a[mt][1] = As[cur][base + 32];
                a[mt][2] = As[cur][base + 64];
                a[mt][3] = As[cur][base + 96];
            }
            #pragma unroll
            for (int nt = 0; nt < 8; ++nt) {
                int base = (nt * 2 + kstep) * 64 + lane;
                b[nt][0] = Ws[cur][base];
                b[nt][1] = Ws[cur][base + 32];
            }
            #pragma unroll
            for (int mt = 0; mt < 2; ++mt)
                #pragma unroll
                for (int nt = 0; nt < 8; ++nt)
                    mma_tf32(dacc[mt][nt], a[mt], b[nt]);
        }
        __syncthreads();
        cur ^= 1;
    }

    // attention vectors for this thread's columns (2 per ntile)
    float2 vs_[8], vd_[8];
    #pragma unroll
    for (int nt = 0; nt < 8; ++nt) {
        vs_[nt] = *(const float2*)&asrc[nBase + nt * 8 + 2 * tig];
        vd_[nt] = *(const float2*)&adst[nBase + nt * 8 + 2 * tig];
    }

    #pragma unroll
    for (int mt = 0; mt < 2; ++mt) {
        int r0 = mBase + w * 32 + mt * 16 + gid;   // row of d[0],d[1]
        int r1 = r0 + 8;                           // row of d[2],d[3]

        float sl = 0.f, dl = 0.f, sh = 0.f, dh = 0.f;
        #pragma unroll
        for (int nt = 0; nt < 8; ++nt) {
            sl += dacc[mt][nt][0] * vs_[nt].x + dacc[mt][nt][1] * vs_[nt].y;
            dl += dacc[mt][nt][0] * vd_[nt].x + dacc[mt][nt][1] * vd_[nt].y;
            sh += dacc[mt][nt][2] * vs_[nt].x + dacc[mt][nt][3] * vs_[nt].y;
            dh += dacc[mt][nt][2] * vd_[nt].x + dacc[mt][nt][3] * vd_[nt].y;
        }
        #pragma unroll
        for (int off = 1; off < 4; off <<= 1) {
            sl += __shfl_xor_sync(0xffffffffu, sl, off);
            dl += __shfl_xor_sync(0xffffffffu, dl, off);
            sh += __shfl_xor_sync(0xffffffffu, sh, off);
            dh += __shfl_xor_sync(0xffffffffu, dh, off);
        }
        if (tig == 0) {
            if (r0 < M) { ss[yoff + r0] = sl; ds[yoff + r0] = dl; }
            if (r1 < M) { ss[yoff + r1] = sh; ds[yoff + r1] = dh; }
        }

        #pragma unroll
        for (int nt = 0; nt < 8; ++nt) {
            int col = nBase + nt * 8 + 2 * tig;
            if (r0 < M) {
                __nv_bfloat162 p = __floats2bfloat162_rn(dacc[mt][nt][0], dacc[mt][nt][1]);
                *(unsigned*)&Cb[(size_t)r0 * Nout + col] = *(unsigned*)&p;
            }
            if (r1 < M) {
                __nv_bfloat162 p = __floats2bfloat162_rn(dacc[mt][nt][2], dacc[mt][nt][3]);
                *(unsigned*)&Cb[(size_t)r1 * Nout + col] = *(unsigned*)&p;
            }
        }
    }
}

// ---------------- fused GAT aggregate + bias + ReLU + LayerNorm ----------------
// 2 nodes per warp: lanes 0-15 -> node 2*wp, lanes 16-31 -> node 2*wp+1.
// Per 16-lane group, VL = F/16 features per lane (uint4/uint2 row loads).
template <int F, bool TWO>
__global__ void agg_kernel(const __nv_bfloat16* __restrict__ hbf,
                           const float* __restrict__ ssp, const float* __restrict__ dsp,
                           const float* __restrict__ bias,
                           const float* __restrict__ gamma,
                           const float* __restrict__ beta,
                           float* __restrict__ out) {
    constexpr int VL = F / 16;                 // 8 (F=128) or 4 (F=64)
    int wp = (blockIdx.x * blockDim.x + threadIdx.x) >> 5;
    int lane = threadIdx.x & 31;
    int grp = lane >> 4;                       // 0/1
    int l = lane & 15;
    int n = wp * 2 + grp;
    if (n >= NN) return;

    float dsn = TWO ? (dsp[n] + dsp[n + NN]) : dsp[n];
    int s0 = g_rowptr[n], s1 = g_rowptr[n + 1];
    int deg = s1 - s0;
    int mdeg = max(deg, __shfl_xor_sync(0xffffffffu, deg, 16));

    auto score = [&](int s) -> float {
        return TWO ? (ssp[s] + ssp[s + NN]) : ssp[s];
    };
    auto ldrow = [&](int row, float* f) {
        if constexpr (VL == 8) {
            uint4 u = ((const uint4*)(hbf + (size_t)row * F))[l];
            __nv_bfloat162* p = (__nv_bfloat162*)&u;
            #pragma unroll
            for (int j = 0; j < 4; ++j) {
                float2 v = __bfloat1622float2(p[j]);
                f[2 * j] = v.x; f[2 * j + 1] = v.y;
            }
        } else {
            uint2 u = ((const uint2*)(hbf + (size_t)row * F))[l];
            __nv_bfloat162* p = (__nv_bfloat162*)&u;
            #pragma unroll
            for (int j = 0; j < 2; ++j) {
                float2 v = __bfloat1622float2(p[j]);
                f[2 * j] = v.x; f[2 * j + 1] = v.y;
            }
        }
    };

    float acc[VL];
    float wself = __expf(lrelu(score(n) + dsn));
    float z = wself;
    {
        float t[VL];
        ldrow(n, t);
        #pragma unroll
        for (int j = 0; j < VL; ++j) acc[j] = wself * t[j];
    }

    for (int i = 0; i < mdeg; i += 4) {
        int s[4]; float sc[4]; bool v[4];
        #pragma unroll
        for (int k = 0; k < 4; ++k) {
            v[k] = (i + k) < deg;
            s[k] = v[k] ? g_csrsrc[s0 + i + k] : n;
        }
        #pragma unroll
        for (int k = 0; k < 4; ++k) sc[k] = score(s[k]);
        float t[4][VL];
        #pragma unroll
        for (int k = 0; k < 4; ++k) ldrow(s[k], t[k]);
        float wv[4];
        #pragma unroll
        for (int k = 0; k < 4; ++k) {
            wv[k] = v[k] ? __expf(lrelu(sc[k] + dsn)) : 0.f;
            z += wv[k];
        }
        #pragma unroll
        for (int j = 0; j < VL; ++j) {
            acc[j] += wv[0] * t[0][j] + wv[1] * t[1][j] + wv[2] * t[2][j] + wv[3] * t[3][j];
        }
    }

    float inv = 1.f / z;
    float vv[VL];
    float sum = 0.f;
    #pragma unroll
    for (int j = 0; j < VL; ++j) {
        vv[j] = fmaxf(acc[j] * inv + bias[l * VL + j], 0.f);  // bias + ReLU
        sum += vv[j];
    }
    #pragma unroll
    for (int off = 8; off > 0; off >>= 1)
        sum += __shfl_xor_sync(0xffffffffu, sum, off);        // 16-lane group reduce
    float mean = sum * (1.f / F);
    float vs = 0.f;
    #pragma unroll
    for (int j = 0; j < VL; ++j) {
        float d = vv[j] - mean;
        vs += d * d;
    }
    #pragma unroll
    for (int off = 8; off > 0; off >>= 1)
        vs += __shfl_xor_sync(0xffffffffu, vs, off);
    float var = vs * (1.f / F);
    float r = rsqrtf(var + 1e-5f);

    if constexpr (VL == 8) {
        float4 g0 = ((const float4*)gamma)[2 * l];
        float4 g1 = ((const float4*)gamma)[2 * l + 1];
        float4 b0 = ((const float4*)beta)[2 * l];
        float4 b1 = ((const float4*)beta)[2 * l + 1];
        float4 o0, o1;
        o0.x = g0.x * (vv[0] - mean) * r + b0.x;
        o0.y = g0.y * (vv[1] - mean) * r + b0.y;
        o0.z = g0.z * (vv[2] - mean) * r + b0.z;
        o0.w = g0.w * (vv[3] - mean) * r + b0.w;
        o1.x = g1.x * (vv[4] - mean) * r + b1.x;
        o1.y = g1.y * (vv[5] - mean) * r + b1.y;
        o1.z = g1.z * (vv[6] - mean) * r + b1.z;
        o1.w = g1.w * (vv[7] - mean) * r + b1.w;
        float4* op = (float4*)&out[(size_t)n * F + 8 * l];
        op[0] = o0; op[1] = o1;
    } else {
        float4 g0 = ((const float4*)gamma)[l];
        float4 b0 = ((const float4*)beta)[l];
        float4 o0;
        o0.x = g0.x * (vv[0] - mean) * r + b0.x;
        o0.y = g0.y * (vv[1] - mean) * r + b0.y;
        o0.z = g0.z * (vv[2] - mean) * r + b0.z;
        o0.w = g0.w * (vv[3] - mean) * r + b0.w;
        *(float4*)&out[(size_t)n * F + 4 * l] = o0;
    }
}

// ---------------- fused pool + head: one block per graph (batch is sorted) ----------------
__global__ void poolhead_kernel(const float* __restrict__ h, const int* __restrict__ batch,
                                const float* __restrict__ Wl, const float* __restrict__ bl,
                                const float* __restrict__ Wc, const float* __restrict__ bc,
                                float* __restrict__ out) {
    __shared__ float psum[4][F2];
    __shared__ float p[F2];
    __shared__ int range[2];
    __shared__ float red[2];
    int g = blockIdx.x;
    int t = threadIdx.x;
    int f = t & 63, q = t >> 6;

    if (t < 2) {
        int val = g + t;
        int lo = 0, hi = NN;
        while (lo < hi) {
            int mid = (lo + hi) >> 1;
            if (batch[mid] < val) lo = mid + 1; else hi = mid;
        }
        range[t] = lo;
    }
    __syncthreads();
    int lo = range[0], hi = range[1];

    float acc = 0.f;
    for (int n = lo + q; n < hi; n += 4) acc += h[(size_t)n * F2 + f];
    psum[q][f] = acc;
    __syncthreads();

    if (t < F2) {
        float cnt = (float)(hi - lo);
        float s = psum[0][t] + psum[1][t] + psum[2][t] + psum[3][t];
        p[t] = s / fmaxf(cnt, 1.f);
    }
    __syncthreads();

    if (t < F2) {
        float lin = bl[t];
        #pragma unroll 8
        for (int j = 0; j < F2; ++j) lin += p[j] * Wl[t * F2 + j];
        float part = lin * Wc[t];
        #pragma unroll
        for (int off = 16; off > 0; off >>= 1)
            part += __shfl_xor_sync(0xffffffffu, part, off);
        if ((t & 31) == 0) red[t >> 5] = part;
    }
    __syncthreads();
    if (t == 0) out[g] = red[0] + red[1] + bc[0];
}

// ---------------- launch ----------------
extern "C" void kernel_launch(void* const* d_in, const int* in_sizes, int n_in,
                              void* d_out, int out_size) {
    const float* x    = (const float*)d_in[0];
    const int*   ei   = (const int*)d_in[1];
    const int*   batch= (const int*)d_in[2];
    const float* W1   = (const float*)d_in[3];
    const float* a1s  = (const float*)d_in[4];
    const float* a1d  = (const float*)d_in[5];
    const float* b1   = (const float*)d_in[6];
    const float* g1   = (const float*)d_in[7];
    const float* be1  = (const float*)d_in[8];
    const float* W2   = (const float*)d_in[9];
    const float* a2s  = (const float*)d_in[10];
    const float* a2d  = (const float*)d_in[11];
    const float* b2   = (const float*)d_in[12];
    const float* g2   = (const float*)d_in[13];
    const float* be2  = (const float*)d_in[14];
    const float* Wl   = (const float*)d_in[15];
    const float* bl   = (const float*)d_in[16];
    const float* Wc   = (const float*)d_in[17];
    const float* bc   = (const float*)d_in[18];
    float* out = (float*)d_out;

    const int* src = ei;
    const int* dst = ei + EE;

    __nv_bfloat16* phbf;
    float *phb, *pss1, *pds1, *pss2, *pds2;
    cudaGetSymbolAddress((void**)&phbf, g_hbf);
    cudaGetSymbolAddress((void**)&phb,  g_hb);
    cudaGetSymbolAddress((void**)&pss1, g_ss1);
    cudaGetSymbolAddress((void**)&pds1, g_ds1);
    cudaGetSymbolAddress((void**)&pss2, g_ss2);
    cudaGetSymbolAddress((void**)&pds2, g_ds2);

    // side stream + fork/join events (created once; host-side objects only)
    static cudaStream_t s1 = nullptr;
    static cudaEvent_t eFork = nullptr, eJoin = nullptr;
    if (s1 == nullptr) {
        cudaStreamCreateWithFlags(&s1, cudaStreamNonBlocking);
        cudaEventCreateWithFlags(&eFork, cudaEventDisableTiming);
        cudaEventCreateWithFlags(&eJoin, cudaEventDisableTiming);
    }

    const int NB = (NN + 255) / 256;   // 157

    // fork: CSR build chain on s1, GEMM1 on main stream
    cudaEventRecord(eFork, 0);
    cudaStreamWaitEvent(s1, eFork, 0);

    count_kernel<<<(EE / 4 + 255) / 256, 256, 0, s1>>>(dst);
    scan_kernel<<<NB, 256, 0, s1>>>();
    scatter_kernel<<<(EE / 4 + 255) / 256, 256, 0, s1>>>(src, dst);
    cudaEventRecord(eJoin, s1);

    // layer 1 GEMM (independent of CSR)
    gemm_tf32<<<dim3((NN + 127) / 128, F1 / 64), 128>>>(
        x, W1, phbf, pss1, pds1, a1s, a1d, NN, F1, 128);

    // join: agg1 needs CSR + GEMM1
    cudaStreamWaitEvent(0, eJoin, 0);
    agg_kernel<F1, true><<<(NN / 2 * 32 + 255) / 256, 256>>>(phbf, pss1, pds1, b1, g1, be1, phb);

    // layer 2
    gemm_tf32<<<dim3((NN + 127) / 128, F2 / 64), 128>>>(
        phb, W2, phbf, pss2, pds2, a2s, a2d, NN, F2, 128);
    agg_kernel<F2, false><<<(NN / 2 * 32 + 255) / 256, 256>>>(phbf, pss2, pds2, b2, g2, be2, phb);

    // fused pool + head
    poolhead_kernel<<<GG, 256>>>(phb, batch, Wl, bl, Wc, bc, out);
}